// round 12
// baseline (speedup 1.0000x reference)
#include <cuda_runtime.h>
#include <math.h>

#define B_    4096
#define T_    24
#define NN    7
#define DYNV  6
#define INV   11
#define H     64
#define FUT   48

#define BT    64            // threads per block, one batch element per block
#define HS    68            // padded row stride (floats)

typedef unsigned long long ull;

// Quad-packed fp32 weights: [(kq*C + c)*4 + q] = W[4kq+q][c]
__device__ float g_wih4[16 * 256 * 4];
__device__ float g_whh4[16 * 256 * 4];
__device__ float g_g1w4[16 * 64 * 4];
__device__ float g_g2w4[16 * 64 * 4];
__device__ float g_enc4[3 * 64 * 4];     // k padded 11 -> 12
__device__ float g_d1w4[16 * 32 * 4];
__device__ float g_d2w2[16 * 6 * 2];     // pair-packed (tiny)

__global__ void pack_weights(const float* __restrict__ w_ih, const float* __restrict__ w_hh,
                             const float* __restrict__ g1w,  const float* __restrict__ g2w,
                             const float* __restrict__ enc_w,
                             const float* __restrict__ d1w,  const float* __restrict__ d2w) {
    int i = blockIdx.x * blockDim.x + threadIdx.x;
    if (i < 16384) {
        int q = i & 3, gc = (i >> 2) & 255, kq = i >> 10;
        g_wih4[i] = w_ih[gc * 64 + 4 * kq + q];     // w_ih is [256][64]
        g_whh4[i] = w_hh[gc * 64 + 4 * kq + q];
    } else if (i < 16384 + 4096) {
        int j = i - 16384;
        int q = j & 3, c = (j >> 2) & 63, kq = j >> 8;
        g_g1w4[j] = g1w[(4 * kq + q) * 64 + c];     // g1w is [64][64]
        g_g2w4[j] = g2w[(4 * kq + q) * 64 + c];
    } else if (i < 16384 + 4096 + 768) {
        int j = i - 16384 - 4096;
        int q = j & 3, c = (j >> 2) & 63, kq = j >> 8;
        int k = 4 * kq + q;
        g_enc4[j] = (k < INV) ? enc_w[k * 64 + c] : 0.f;
    } else if (i < 16384 + 4096 + 768 + 2048) {
        int j = i - 16384 - 4096 - 768;
        int q = j & 3, c = (j >> 2) & 31, kq = j >> 7;
        g_d1w4[j] = d1w[(4 * kq + q) * 32 + c];
    } else if (i < 16384 + 4096 + 768 + 2048 + 192) {
        int j = i - (16384 + 4096 + 768 + 2048);
        int kp = j / 12, rr = j - kp * 12, d = rr >> 1, p = rr & 1;
        g_d2w2[j] = d2w[(2 * kp + p) * 6 + d];
    }
}

// ---------- helpers ----------
__device__ __forceinline__ ulonglong2 ldg4(const float* p) {
    return __ldg(reinterpret_cast<const ulonglong2*>(p));
}
__device__ __forceinline__ ulonglong2 lds4(const float* p) {
    return *reinterpret_cast<const ulonglong2*>(p);
}
__device__ __forceinline__ ull ldsm2(const float* p) { return *reinterpret_cast<const ull*>(p); }
__device__ __forceinline__ ull ldg2(const float* p)  { return __ldg(reinterpret_cast<const ull*>(p)); }
__device__ __forceinline__ void ffma2(ull& d, ull a, ull b) {
    asm("fma.rn.f32x2 %0, %1, %2, %3;" : "=l"(d) : "l"(a), "l"(b), "l"(d));
}
__device__ __forceinline__ float hsum(ull v) {
    float2 f = *reinterpret_cast<float2*>(&v);
    return f.x + f.y;
}
__device__ __forceinline__ float sigm_f(float x) { return __fdividef(1.f, 1.f + __expf(-x)); }
__device__ __forceinline__ float tanh_f(float x) {
    float e = __expf(2.f * x);
    return 1.f - __fdividef(2.f, e + 1.f);
}

struct __align__(16) Smem {
    float xt[NN][12];        // in rollout: cols 0..5 = pred (autoregressive), 6..10 = stat, 11 = 0
    float A[NN][HS];
    float Bv[NN][HS];
    float hx[NN][HS];
    float adjn[49];
    float deg[8];
};

// GCN layer fused: out[i][c] = relu( sum_j adjn[i][j] * (in @ W)[j][c] + bias[c] )
// GEMM intermediate for column c stays in registers of thread c.
__device__ __forceinline__ void gcn_fused(const Smem* s, const float (*in)[HS],
                                          const float* __restrict__ w4,
                                          float (*out)[HS],
                                          const float* __restrict__ bias, int c) {
    ull acc[NN] = {};
    #pragma unroll
    for (int kq = 0; kq < 16; kq++) {
        ulonglong2 w = ldg4(&w4[(kq * 64 + c) * 4]);
        #pragma unroll
        for (int r = 0; r < NN; r++) {
            ulonglong2 a = lds4(&in[r][4 * kq]);
            ffma2(acc[r], a.x, w.x);
            ffma2(acc[r], a.y, w.y);
        }
    }
    float bv[NN];
    #pragma unroll
    for (int r = 0; r < NN; r++) bv[r] = hsum(acc[r]);
    float bb = __ldg(&bias[c]);
    #pragma unroll
    for (int i = 0; i < NN; i++) {
        float a = bb;
        #pragma unroll
        for (int j = 0; j < NN; j++)
            a = fmaf(s->adjn[i * 7 + j], bv[j], a);
        out[i][c] = fmaxf(a, 0.f);
    }
}

// One cell step. xt filled+synced on entry; hx/creg updated+synced on exit.
// creg = this thread's cx[0..6][c] (thread-private state).
__device__ __forceinline__ void cell(Smem* s, int c, float* creg,
        const float* __restrict__ enc_b,
        const float* __restrict__ g1b, const float* __restrict__ g2b,
        const float* __restrict__ b_ih, const float* __restrict__ b_hh) {
    // encoder -> A
    {
        ull acc[NN] = {};
        #pragma unroll
        for (int kq = 0; kq < 3; kq++) {
            ulonglong2 w = ldg4(&g_enc4[(kq * 64 + c) * 4]);
            #pragma unroll
            for (int r = 0; r < NN; r++) {
                ulonglong2 a = lds4(&s->xt[r][4 * kq]);
                ffma2(acc[r], a.x, w.x);
                ffma2(acc[r], a.y, w.y);
            }
        }
        float bb = __ldg(&enc_b[c]);
        #pragma unroll
        for (int r = 0; r < NN; r++)
            s->A[r][c] = fmaxf(hsum(acc[r]) + bb, 0.f);
    }
    __syncthreads();
    gcn_fused(s, s->A, g_g1w4, s->Bv, g1b, c);      // A -> Bv
    __syncthreads();
    gcn_fused(s, s->Bv, g_g2w4, s->A, g2b, c);      // Bv -> A
    __syncthreads();

    // LSTM gates, single pass: thread c owns cols {c, c+64, c+128, c+192}.
    {
        ull a0[NN] = {}, a1[NN] = {}, a2[NN] = {}, a3[NN] = {};
        #pragma unroll 8
        for (int kq = 0; kq < 16; kq++) {
            ulonglong2 wi0 = ldg4(&g_wih4[(kq * 256 + c) * 4]);
            ulonglong2 wh0 = ldg4(&g_whh4[(kq * 256 + c) * 4]);
            ulonglong2 wi1 = ldg4(&g_wih4[(kq * 256 + 64 + c) * 4]);
            ulonglong2 wh1 = ldg4(&g_whh4[(kq * 256 + 64 + c) * 4]);
            ulonglong2 wi2 = ldg4(&g_wih4[(kq * 256 + 128 + c) * 4]);
            ulonglong2 wh2 = ldg4(&g_whh4[(kq * 256 + 128 + c) * 4]);
            ulonglong2 wi3 = ldg4(&g_wih4[(kq * 256 + 192 + c) * 4]);
            ulonglong2 wh3 = ldg4(&g_whh4[(kq * 256 + 192 + c) * 4]);
            #pragma unroll
            for (int r = 0; r < NN; r++) {
                ulonglong2 aA = lds4(&s->A[r][4 * kq]);
                ulonglong2 aH = lds4(&s->hx[r][4 * kq]);
                ffma2(a0[r], aA.x, wi0.x); ffma2(a0[r], aA.y, wi0.y);
                ffma2(a0[r], aH.x, wh0.x); ffma2(a0[r], aH.y, wh0.y);
                ffma2(a1[r], aA.x, wi1.x); ffma2(a1[r], aA.y, wi1.y);
                ffma2(a1[r], aH.x, wh1.x); ffma2(a1[r], aH.y, wh1.y);
                ffma2(a2[r], aA.x, wi2.x); ffma2(a2[r], aA.y, wi2.y);
                ffma2(a2[r], aH.x, wh2.x); ffma2(a2[r], aH.y, wh2.y);
                ffma2(a3[r], aA.x, wi3.x); ffma2(a3[r], aA.y, wi3.y);
                ffma2(a3[r], aH.x, wh3.x); ffma2(a3[r], aH.y, wh3.y);
            }
        }
        float bI = __ldg(&b_ih[c])       + __ldg(&b_hh[c]);
        float bF = __ldg(&b_ih[64 + c])  + __ldg(&b_hh[64 + c]);
        float bG = __ldg(&b_ih[128 + c]) + __ldg(&b_hh[128 + c]);
        float bO = __ldg(&b_ih[192 + c]) + __ldg(&b_hh[192 + c]);
        __syncthreads();   // all A/hx reads complete before hx overwrite
        #pragma unroll
        for (int r = 0; r < NN; r++) {
            float gi = sigm_f(hsum(a0[r]) + bI);
            float gf = sigm_f(hsum(a1[r]) + bF);
            float gg = tanh_f(hsum(a2[r]) + bG);
            float go = sigm_f(hsum(a3[r]) + bO);
            float cc = gf * creg[r] + gi * gg;
            creg[r] = cc;
            s->hx[r][c] = go * tanh_f(cc);
        }
    }
    __syncthreads();
}

__global__ void __launch_bounds__(BT, 9)
stgnn_kernel(const float* __restrict__ xh,    const float* __restrict__ adj,
             const float* __restrict__ enc_b,
             const float* __restrict__ g1b,   const float* __restrict__ g2b,
             const float* __restrict__ b_ih,  const float* __restrict__ b_hh,
             const float* __restrict__ d1b,   const float* __restrict__ d2b,
             float* __restrict__ out) {
    __shared__ Smem sm;
    Smem* s = &sm;
    const int c = threadIdx.x;     // 0..63
    const int b = blockIdx.x;      // batch element

    // ---- normalized adjacency + zero state ----
    if (c < 49) {
        int i = c / 7, j = c - i * 7;
        s->adjn[c] = (i == j) ? 1.0f : __ldg(&adj[b * 49 + c]);
    }
    float creg[NN];                // cx[0..6][c] in registers (thread-private)
    #pragma unroll
    for (int r = 0; r < NN; r++) { s->hx[r][c] = 0.f; creg[r] = 0.f; }
    __syncthreads();
    if (c < NN) {
        float sum = 0.f;
        #pragma unroll
        for (int j = 0; j < NN; j++) sum += s->adjn[c * 7 + j];
        s->deg[c] = rsqrtf(fmaxf(sum, 1.0f));
    }
    __syncthreads();
    if (c < 49) {
        int i = c / 7, j = c - i * 7;
        s->adjn[c] *= s->deg[i] * s->deg[j];
    }
    __syncthreads();

    // ---- history scan ----
    #pragma unroll 1
    for (int t = 0; t < T_; t++) {
        for (int idx = c; idx < NN * 12; idx += BT) {
            int r = idx / 12, k = idx - r * 12;
            float v = 0.f;
            if (k < INV) v = __ldg(&xh[((b * T_ + t) * NN + r) * INV + k]);
            s->xt[r][k] = v;
        }
        __syncthreads();
        cell(s, c, creg, enc_b, g1b, g2b, b_ih, b_hh);
    }

    // ---- seed xt with last history step: cols 0..5 = pred, 6..10 = stat, 11 = 0 ----
    for (int idx = c; idx < NN * 12; idx += BT) {
        int r = idx / 12, k = idx - r * 12;
        float v = 0.f;
        if (k < INV) v = __ldg(&xh[((b * T_ + (T_ - 1)) * NN + r) * INV + k]);
        s->xt[r][k] = v;
    }
    __syncthreads();

    // ---- future rollout: xt carries the autoregressive state in place ----
    #pragma unroll 1
    for (int f = 0; f < FUT; f++) {
        cell(s, c, creg, enc_b, g1b, g2b, b_ih, b_hh);

        // decoder layer 1: Bv[:, :32] = relu(hx @ d1w + d1b); ALL 64 threads.
        // thread c: col = c&31, rows {0..3} if c<32 else {4..6}.
        {
            int col = c & 31;
            int r0 = (c < 32) ? 0 : 4;
            int nr = (c < 32) ? 4 : 3;
            ull acc[4] = {};
            #pragma unroll
            for (int kq = 0; kq < 16; kq++) {
                ulonglong2 w = ldg4(&g_d1w4[(kq * 32 + col) * 4]);
                #pragma unroll
                for (int i = 0; i < 4; i++) {
                    if (i < nr) {
                        ulonglong2 a = lds4(&s->hx[r0 + i][4 * kq]);
                        ffma2(acc[i], a.x, w.x);
                        ffma2(acc[i], a.y, w.y);
                    }
                }
            }
            float bb = __ldg(&d1b[col]);
            #pragma unroll
            for (int i = 0; i < 4; i++)
                if (i < nr)
                    s->Bv[r0 + i][col] = fmaxf(hsum(acc[i]) + bb, 0.f);
        }
        __syncthreads();

        // decoder layer 2 + residual + clip; update xt in place + write output (42 threads)
        if (c < NN * DYNV) {
            int r = c / DYNV, d = c - r * DYNV;
            ull acc = 0;
            float z = 0.f;
            asm("mov.b64 %0, {%1, %1};" : "=l"(acc) : "f"(z));
            #pragma unroll
            for (int kp = 0; kp < 16; kp++)
                ffma2(acc, ldsm2(&s->Bv[r][2 * kp]), ldg2(&g_d2w2[(kp * 6 + d) * 2]));
            float res = tanh_f(hsum(acc) + __ldg(&d2b[d])) * 0.05f;
            float p = fminf(fmaxf(s->xt[r][d] + res, 0.f), 1.f);
            s->xt[r][d] = p;
            out[((b * FUT + f) * NN + r) * DYNV + d] = p;
        }
        __syncthreads();
    }
}

extern "C" void kernel_launch(void* const* d_in, const int* in_sizes, int n_in,
                              void* d_out, int out_size) {
    const float* xh    = (const float*)d_in[0];
    const float* adj   = (const float*)d_in[1];
    const float* enc_w = (const float*)d_in[2];
    const float* enc_b = (const float*)d_in[3];
    const float* g1w   = (const float*)d_in[4];
    const float* g1b   = (const float*)d_in[5];
    const float* g2w   = (const float*)d_in[6];
    const float* g2b   = (const float*)d_in[7];
    const float* w_ih  = (const float*)d_in[8];
    const float* w_hh  = (const float*)d_in[9];
    const float* b_ih  = (const float*)d_in[10];
    const float* b_hh  = (const float*)d_in[11];
    const float* d1w   = (const float*)d_in[12];
    const float* d1b   = (const float*)d_in[13];
    const float* d2w   = (const float*)d_in[14];
    const float* d2b   = (const float*)d_in[15];
    float* out = (float*)d_out;

    pack_weights<<<(23488 + 255) / 256, 256>>>(w_ih, w_hh, g1w, g2w, enc_w, d1w, d2w);
    stgnn_kernel<<<B_, BT>>>(xh, adj, enc_b, g1b, g2b, b_ih, b_hh, d1b, d2b, out);
}

// round 14
// speedup vs baseline: 1.5019x; 1.5019x over previous
#include <cuda_runtime.h>
#include <math.h>

#define B_    4096
#define T_    24
#define NN    7
#define DYNV  6
#define INV   11
#define H     64
#define FUT   48

#define BT    64            // threads per block, one batch element per block
#define HS    68            // padded row stride (floats)

typedef unsigned long long ull;

// Quad-packed fp32 weights: [(kq*C + c)*4 + q] = W[4kq+q][c]
__device__ float g_wih4[16 * 256 * 4];
__device__ float g_whh4[16 * 256 * 4];
__device__ float g_g1w4[16 * 64 * 4];
__device__ float g_g2w4[16 * 64 * 4];
__device__ float g_enc4[3 * 64 * 4];     // k padded 11 -> 12
__device__ float g_d1w4[16 * 32 * 4];
__device__ float g_d2w2[16 * 6 * 2];     // pair-packed (tiny)

__global__ void pack_weights(const float* __restrict__ w_ih, const float* __restrict__ w_hh,
                             const float* __restrict__ g1w,  const float* __restrict__ g2w,
                             const float* __restrict__ enc_w,
                             const float* __restrict__ d1w,  const float* __restrict__ d2w) {
    int i = blockIdx.x * blockDim.x + threadIdx.x;
    if (i < 16384) {
        int q = i & 3, gc = (i >> 2) & 255, kq = i >> 10;
        g_wih4[i] = w_ih[gc * 64 + 4 * kq + q];     // w_ih is [256][64]
        g_whh4[i] = w_hh[gc * 64 + 4 * kq + q];
    } else if (i < 16384 + 4096) {
        int j = i - 16384;
        int q = j & 3, c = (j >> 2) & 63, kq = j >> 8;
        g_g1w4[j] = g1w[(4 * kq + q) * 64 + c];     // g1w is [64][64]
        g_g2w4[j] = g2w[(4 * kq + q) * 64 + c];
    } else if (i < 16384 + 4096 + 768) {
        int j = i - 16384 - 4096;
        int q = j & 3, c = (j >> 2) & 63, kq = j >> 8;
        int k = 4 * kq + q;
        g_enc4[j] = (k < INV) ? enc_w[k * 64 + c] : 0.f;
    } else if (i < 16384 + 4096 + 768 + 2048) {
        int j = i - 16384 - 4096 - 768;
        int q = j & 3, c = (j >> 2) & 31, kq = j >> 7;
        g_d1w4[j] = d1w[(4 * kq + q) * 32 + c];
    } else if (i < 16384 + 4096 + 768 + 2048 + 192) {
        int j = i - (16384 + 4096 + 768 + 2048);
        int kp = j / 12, rr = j - kp * 12, d = rr >> 1, p = rr & 1;
        g_d2w2[j] = d2w[(2 * kp + p) * 6 + d];
    }
}

// ---------- helpers ----------
__device__ __forceinline__ ulonglong2 ldg4(const float* p) {
    return __ldg(reinterpret_cast<const ulonglong2*>(p));
}
__device__ __forceinline__ ulonglong2 lds4(const float* p) {
    return *reinterpret_cast<const ulonglong2*>(p);
}
__device__ __forceinline__ ull ldsm2(const float* p) { return *reinterpret_cast<const ull*>(p); }
__device__ __forceinline__ ull ldg2(const float* p)  { return __ldg(reinterpret_cast<const ull*>(p)); }
__device__ __forceinline__ void ffma2(ull& d, ull a, ull b) {
    asm("fma.rn.f32x2 %0, %1, %2, %3;" : "=l"(d) : "l"(a), "l"(b), "l"(d));
}
__device__ __forceinline__ float hsum(ull v) {
    float2 f = *reinterpret_cast<float2*>(&v);
    return f.x + f.y;
}
__device__ __forceinline__ float sigm_f(float x) { return __fdividef(1.f, 1.f + __expf(-x)); }
__device__ __forceinline__ float tanh_f(float x) {
    float e = __expf(2.f * x);
    return 1.f - __fdividef(2.f, e + 1.f);
}

struct __align__(16) Smem {
    float xt[NN][12];        // in rollout: cols 0..5 = pred (autoregressive), 6..10 = stat, 11 = 0
    float A[NN][HS];
    float Bv[NN][HS];
    float hx[NN][HS];
    float adjn[49];
    float deg[8];
};

// GCN layer fused: out[i][c] = relu( sum_j adjn[i][j] * (in @ W)[j][c] + bias[c] )
// GEMM intermediate for column c stays in registers of thread c.
__device__ __forceinline__ void gcn_fused(const Smem* s, const float (*in)[HS],
                                          const float* __restrict__ w4,
                                          float (*out)[HS],
                                          const float* __restrict__ bias, int c) {
    ull acc[NN] = {};
    #pragma unroll
    for (int kq = 0; kq < 16; kq++) {
        ulonglong2 w = ldg4(&w4[(kq * 64 + c) * 4]);
        #pragma unroll
        for (int r = 0; r < NN; r++) {
            ulonglong2 a = lds4(&in[r][4 * kq]);
            ffma2(acc[r], a.x, w.x);
            ffma2(acc[r], a.y, w.y);
        }
    }
    float bv[NN];
    #pragma unroll
    for (int r = 0; r < NN; r++) bv[r] = hsum(acc[r]);
    float bb = __ldg(&bias[c]);
    #pragma unroll
    for (int i = 0; i < NN; i++) {
        float a = bb;
        #pragma unroll
        for (int j = 0; j < NN; j++)
            a = fmaf(s->adjn[i * 7 + j], bv[j], a);
        out[i][c] = fmaxf(a, 0.f);
    }
}

// One cell step. xt filled+synced on entry; hx/creg updated+synced on exit.
// creg = this thread's cx[0..6][c] (thread-private state).
__device__ __forceinline__ void cell(Smem* s, int c, float* creg,
        const float* __restrict__ enc_b,
        const float* __restrict__ g1b, const float* __restrict__ g2b,
        const float* __restrict__ b_ih, const float* __restrict__ b_hh) {
    // encoder -> A
    {
        ull acc[NN] = {};
        #pragma unroll
        for (int kq = 0; kq < 3; kq++) {
            ulonglong2 w = ldg4(&g_enc4[(kq * 64 + c) * 4]);
            #pragma unroll
            for (int r = 0; r < NN; r++) {
                ulonglong2 a = lds4(&s->xt[r][4 * kq]);
                ffma2(acc[r], a.x, w.x);
                ffma2(acc[r], a.y, w.y);
            }
        }
        float bb = __ldg(&enc_b[c]);
        #pragma unroll
        for (int r = 0; r < NN; r++)
            s->A[r][c] = fmaxf(hsum(acc[r]) + bb, 0.f);
    }
    __syncthreads();
    gcn_fused(s, s->A, g_g1w4, s->Bv, g1b, c);      // A -> Bv
    __syncthreads();
    gcn_fused(s, s->Bv, g_g2w4, s->A, g2b, c);      // Bv -> A
    __syncthreads();

    // LSTM gates, single pass: thread c owns cols {c, c+64, c+128, c+192}.
    {
        ull a0[NN] = {}, a1[NN] = {}, a2[NN] = {}, a3[NN] = {};
        #pragma unroll 8
        for (int kq = 0; kq < 16; kq++) {
            ulonglong2 wi0 = ldg4(&g_wih4[(kq * 256 + c) * 4]);
            ulonglong2 wh0 = ldg4(&g_whh4[(kq * 256 + c) * 4]);
            ulonglong2 wi1 = ldg4(&g_wih4[(kq * 256 + 64 + c) * 4]);
            ulonglong2 wh1 = ldg4(&g_whh4[(kq * 256 + 64 + c) * 4]);
            ulonglong2 wi2 = ldg4(&g_wih4[(kq * 256 + 128 + c) * 4]);
            ulonglong2 wh2 = ldg4(&g_whh4[(kq * 256 + 128 + c) * 4]);
            ulonglong2 wi3 = ldg4(&g_wih4[(kq * 256 + 192 + c) * 4]);
            ulonglong2 wh3 = ldg4(&g_whh4[(kq * 256 + 192 + c) * 4]);
            #pragma unroll
            for (int r = 0; r < NN; r++) {
                ulonglong2 aA = lds4(&s->A[r][4 * kq]);
                ulonglong2 aH = lds4(&s->hx[r][4 * kq]);
                ffma2(a0[r], aA.x, wi0.x); ffma2(a0[r], aA.y, wi0.y);
                ffma2(a0[r], aH.x, wh0.x); ffma2(a0[r], aH.y, wh0.y);
                ffma2(a1[r], aA.x, wi1.x); ffma2(a1[r], aA.y, wi1.y);
                ffma2(a1[r], aH.x, wh1.x); ffma2(a1[r], aH.y, wh1.y);
                ffma2(a2[r], aA.x, wi2.x); ffma2(a2[r], aA.y, wi2.y);
                ffma2(a2[r], aH.x, wh2.x); ffma2(a2[r], aH.y, wh2.y);
                ffma2(a3[r], aA.x, wi3.x); ffma2(a3[r], aA.y, wi3.y);
                ffma2(a3[r], aH.x, wh3.x); ffma2(a3[r], aH.y, wh3.y);
            }
        }
        float bI = __ldg(&b_ih[c])       + __ldg(&b_hh[c]);
        float bF = __ldg(&b_ih[64 + c])  + __ldg(&b_hh[64 + c]);
        float bG = __ldg(&b_ih[128 + c]) + __ldg(&b_hh[128 + c]);
        float bO = __ldg(&b_ih[192 + c]) + __ldg(&b_hh[192 + c]);
        __syncthreads();   // all A/hx reads complete before hx overwrite
        #pragma unroll
        for (int r = 0; r < NN; r++) {
            float gi = sigm_f(hsum(a0[r]) + bI);
            float gf = sigm_f(hsum(a1[r]) + bF);
            float gg = tanh_f(hsum(a2[r]) + bG);
            float go = sigm_f(hsum(a3[r]) + bO);
            float cc = gf * creg[r] + gi * gg;
            creg[r] = cc;
            s->hx[r][c] = go * tanh_f(cc);
        }
    }
    __syncthreads();
}

__global__ void __launch_bounds__(BT, 8)
stgnn_kernel(const float* __restrict__ xh,    const float* __restrict__ adj,
             const float* __restrict__ enc_b,
             const float* __restrict__ g1b,   const float* __restrict__ g2b,
             const float* __restrict__ b_ih,  const float* __restrict__ b_hh,
             const float* __restrict__ d1b,   const float* __restrict__ d2b,
             float* __restrict__ out) {
    __shared__ Smem sm;
    Smem* s = &sm;
    const int c = threadIdx.x;     // 0..63
    const int b = blockIdx.x;      // batch element

    // ---- normalized adjacency + zero state ----
    if (c < 49) {
        int i = c / 7, j = c - i * 7;
        s->adjn[c] = (i == j) ? 1.0f : __ldg(&adj[b * 49 + c]);
    }
    float creg[NN];                // cx[0..6][c] in registers (thread-private)
    #pragma unroll
    for (int r = 0; r < NN; r++) { s->hx[r][c] = 0.f; creg[r] = 0.f; }
    __syncthreads();
    if (c < NN) {
        float sum = 0.f;
        #pragma unroll
        for (int j = 0; j < NN; j++) sum += s->adjn[c * 7 + j];
        s->deg[c] = rsqrtf(fmaxf(sum, 1.0f));
    }
    __syncthreads();
    if (c < 49) {
        int i = c / 7, j = c - i * 7;
        s->adjn[c] *= s->deg[i] * s->deg[j];
    }
    __syncthreads();

    // ---- history scan ----
    #pragma unroll 1
    for (int t = 0; t < T_; t++) {
        for (int idx = c; idx < NN * 12; idx += BT) {
            int r = idx / 12, k = idx - r * 12;
            float v = 0.f;
            if (k < INV) v = __ldg(&xh[((b * T_ + t) * NN + r) * INV + k]);
            s->xt[r][k] = v;
        }
        __syncthreads();
        cell(s, c, creg, enc_b, g1b, g2b, b_ih, b_hh);
    }

    // ---- seed xt with last history step: cols 0..5 = pred, 6..10 = stat, 11 = 0 ----
    for (int idx = c; idx < NN * 12; idx += BT) {
        int r = idx / 12, k = idx - r * 12;
        float v = 0.f;
        if (k < INV) v = __ldg(&xh[((b * T_ + (T_ - 1)) * NN + r) * INV + k]);
        s->xt[r][k] = v;
    }
    __syncthreads();

    // ---- future rollout: xt carries the autoregressive state in place ----
    #pragma unroll 1
    for (int f = 0; f < FUT; f++) {
        cell(s, c, creg, enc_b, g1b, g2b, b_ih, b_hh);

        // decoder layer 1: Bv[:, :32] = relu(hx @ d1w + d1b); ALL 64 threads.
        // thread c: col = c&31, rows {0..3} if c<32 else {4..6}.
        {
            int col = c & 31;
            int r0 = (c < 32) ? 0 : 4;
            int nr = (c < 32) ? 4 : 3;
            ull acc[4] = {};
            #pragma unroll
            for (int kq = 0; kq < 16; kq++) {
                ulonglong2 w = ldg4(&g_d1w4[(kq * 32 + col) * 4]);
                #pragma unroll
                for (int i = 0; i < 4; i++) {
                    if (i < nr) {
                        ulonglong2 a = lds4(&s->hx[r0 + i][4 * kq]);
                        ffma2(acc[i], a.x, w.x);
                        ffma2(acc[i], a.y, w.y);
                    }
                }
            }
            float bb = __ldg(&d1b[col]);
            #pragma unroll
            for (int i = 0; i < 4; i++)
                if (i < nr)
                    s->Bv[r0 + i][col] = fmaxf(hsum(acc[i]) + bb, 0.f);
        }
        __syncthreads();

        // decoder layer 2 + residual + clip; update xt in place + write output (42 threads)
        if (c < NN * DYNV) {
            int r = c / DYNV, d = c - r * DYNV;
            ull acc = 0;
            float z = 0.f;
            asm("mov.b64 %0, {%1, %1};" : "=l"(acc) : "f"(z));
            #pragma unroll
            for (int kp = 0; kp < 16; kp++)
                ffma2(acc, ldsm2(&s->Bv[r][2 * kp]), ldg2(&g_d2w2[(kp * 6 + d) * 2]));
            float res = tanh_f(hsum(acc) + __ldg(&d2b[d])) * 0.05f;
            float p = fminf(fmaxf(s->xt[r][d] + res, 0.f), 1.f);
            s->xt[r][d] = p;
            out[((b * FUT + f) * NN + r) * DYNV + d] = p;
        }
        __syncthreads();
    }
}

extern "C" void kernel_launch(void* const* d_in, const int* in_sizes, int n_in,
                              void* d_out, int out_size) {
    const float* xh    = (const float*)d_in[0];
    const float* adj   = (const float*)d_in[1];
    const float* enc_w = (const float*)d_in[2];
    const float* enc_b = (const float*)d_in[3];
    const float* g1w   = (const float*)d_in[4];
    const float* g1b   = (const float*)d_in[5];
    const float* g2w   = (const float*)d_in[6];
    const float* g2b   = (const float*)d_in[7];
    const float* w_ih  = (const float*)d_in[8];
    const float* w_hh  = (const float*)d_in[9];
    const float* b_ih  = (const float*)d_in[10];
    const float* b_hh  = (const float*)d_in[11];
    const float* d1w   = (const float*)d_in[12];
    const float* d1b   = (const float*)d_in[13];
    const float* d2w   = (const float*)d_in[14];
    const float* d2b   = (const float*)d_in[15];
    float* out = (float*)d_out;

    pack_weights<<<(23488 + 255) / 256, 256>>>(w_ih, w_hh, g1w, g2w, enc_w, d1w, d2w);
    stgnn_kernel<<<B_, BT>>>(xh, adj, enc_b, g1b, g2b, b_ih, b_hh, d1b, d2b, out);
}

// round 15
// speedup vs baseline: 2.3277x; 1.5498x over previous
#include <cuda_runtime.h>
#include <math.h>
#include <stdint.h>

#define B_    4096
#define T_    24
#define NN    7
#define DYNV  6
#define INV   11
#define H     64
#define FUT   48

#define EPB   4              // batch elements per block
#define RWS   28             // real rows = EPB * NN
#define BT    256            // threads per block (8 warps)
#define HS    68             // padded row stride (floats)
#define GS    260            // gate buffer row stride

typedef unsigned long long ull;

// mma-packed LSTM weights (tf32-rounded), lane order for m16n8k8 col-major B frags:
// index = ((kt*32 + nt)*32 + lane)*2 + p ;  value = W[kt*8 + (lane&3) + 4p][nt*8 + (lane>>2)]
__device__ float g_wihP[8 * 32 * 32 * 2];
__device__ float g_whhP[8 * 32 * 32 * 2];
// quad-packed fp32 weights for FFMA2 paths
__device__ float g_g1w4[16 * 64 * 4];
__device__ float g_g2w4[16 * 64 * 4];
__device__ float g_enc4[3 * 64 * 4];
__device__ float g_d1w4[16 * 32 * 4];
__device__ float g_d2w2[16 * 6 * 2];

__device__ __forceinline__ float tf32r(float x) {
    uint32_t r; asm("cvt.rna.tf32.f32 %0, %1;" : "=r"(r) : "f"(x));
    return __uint_as_float(r);
}

__global__ void pack_weights(const float* __restrict__ w_ih, const float* __restrict__ w_hh,
                             const float* __restrict__ g1w,  const float* __restrict__ g2w,
                             const float* __restrict__ enc_w,
                             const float* __restrict__ d1w,  const float* __restrict__ d2w) {
    int i = blockIdx.x * blockDim.x + threadIdx.x;
    if (i < 16384) {
        int p = i & 1, lane = (i >> 1) & 31, nt = (i >> 6) & 31, kt = i >> 11;
        int k = kt * 8 + (lane & 3) + p * 4;
        int n = nt * 8 + (lane >> 2);
        g_wihP[i] = tf32r(w_ih[n * 64 + k]);    // w_ih is [256][64]
        g_whhP[i] = tf32r(w_hh[n * 64 + k]);
    } else if (i < 16384 + 4096) {
        int j = i - 16384;
        int q = j & 3, c = (j >> 2) & 63, kq = j >> 8;
        g_g1w4[j] = g1w[(4 * kq + q) * 64 + c];
        g_g2w4[j] = g2w[(4 * kq + q) * 64 + c];
    } else if (i < 16384 + 4096 + 768) {
        int j = i - 16384 - 4096;
        int q = j & 3, c = (j >> 2) & 63, kq = j >> 8;
        int k = 4 * kq + q;
        g_enc4[j] = (k < INV) ? enc_w[k * 64 + c] : 0.f;
    } else if (i < 16384 + 4096 + 768 + 2048) {
        int j = i - 16384 - 4096 - 768;
        int q = j & 3, c = (j >> 2) & 31, kq = j >> 7;
        g_d1w4[j] = d1w[(4 * kq + q) * 32 + c];
    } else if (i < 16384 + 4096 + 768 + 2048 + 192) {
        int j = i - (16384 + 4096 + 768 + 2048);
        int kp = j / 12, rr = j - kp * 12, d = rr >> 1, p = rr & 1;
        g_d2w2[j] = d2w[(2 * kp + p) * 6 + d];
    }
}

// ---------- helpers ----------
__device__ __forceinline__ ulonglong2 ldg4(const float* p) {
    return __ldg(reinterpret_cast<const ulonglong2*>(p));
}
__device__ __forceinline__ ulonglong2 lds4(const float* p) {
    return *reinterpret_cast<const ulonglong2*>(p);
}
__device__ __forceinline__ ull ldsm2(const float* p) { return *reinterpret_cast<const ull*>(p); }
__device__ __forceinline__ ull ldg2(const float* p)  { return __ldg(reinterpret_cast<const ull*>(p)); }
__device__ __forceinline__ void ffma2(ull& d, ull a, ull b) {
    asm("fma.rn.f32x2 %0, %1, %2, %3;" : "=l"(d) : "l"(a), "l"(b), "l"(d));
}
__device__ __forceinline__ float hsum(ull v) {
    float2 f = *reinterpret_cast<float2*>(&v);
    return f.x + f.y;
}
__device__ __forceinline__ uint32_t cvtt(float x) {
    uint32_t r; asm("cvt.rna.tf32.f32 %0, %1;" : "=r"(r) : "f"(x));
    return r;
}
__device__ __forceinline__ void mma8(float* d, const uint32_t* a, uint32_t b0, uint32_t b1) {
    asm("mma.sync.aligned.m16n8k8.row.col.f32.tf32.tf32.f32 "
        "{%0,%1,%2,%3},{%4,%5,%6,%7},{%8,%9},{%0,%1,%2,%3};"
        : "+f"(d[0]), "+f"(d[1]), "+f"(d[2]), "+f"(d[3])
        : "r"(a[0]), "r"(a[1]), "r"(a[2]), "r"(a[3]), "r"(b0), "r"(b1));
}
__device__ __forceinline__ float sigm_f(float x) { return __fdividef(1.f, 1.f + __expf(-x)); }
__device__ __forceinline__ float tanh_f(float x) {
    float e = __expf(2.f * x);
    return 1.f - __fdividef(2.f, e + 1.f);
}

struct __align__(16) Smem {
    float xt[RWS][12];
    float A[32][HS];     // rows 28..31 = zero pad (set once, never rewritten)
    float hx[32][HS];    // rows 28..31 = zero pad
    float Bv[RWS][HS];
    float g[32][GS];     // gate pre-activations (mma output)
    float adjn[EPB][49];
    float deg[EPB][8];
    float pred[RWS][DYNV];
    float stat[RWS][8];
};

// GCN layer fused: out[r0+i][c] = relu( sum_j adje[i*7+j] * (in @ W)[r0+j][c] + bb )
__device__ __forceinline__ void gcn_fused(const float (*in)[HS], const float* __restrict__ w4,
                                          float (*out)[HS], float bb, int r0, int c,
                                          const float* adje) {
    ull acc[NN] = {};
    #pragma unroll
    for (int kq = 0; kq < 16; kq++) {
        ulonglong2 w = ldg4(&w4[(kq * 64 + c) * 4]);
        #pragma unroll
        for (int r = 0; r < NN; r++) {
            ulonglong2 a = lds4(&in[r0 + r][4 * kq]);
            ffma2(acc[r], a.x, w.x);
            ffma2(acc[r], a.y, w.y);
        }
    }
    float bv[NN];
    #pragma unroll
    for (int r = 0; r < NN; r++) bv[r] = hsum(acc[r]);
    #pragma unroll
    for (int i = 0; i < NN; i++) {
        float a = bb;
        #pragma unroll
        for (int j = 0; j < NN; j++)
            a = fmaf(adje[i * 7 + j], bv[j], a);
        out[r0 + i][c] = fmaxf(a, 0.f);
    }
}

// One cell step. xt filled+synced on entry; hx/creg updated+synced on exit.
__device__ __forceinline__ void cell(Smem* s, int tid, float* creg,
        float bEnc, float bG1, float bG2,
        float bI, float bF, float bG, float bO) {
    const int e = tid >> 6, c = tid & 63, r0 = e * NN;
    const float* adje = &s->adjn[e][0];

    // encoder -> A
    {
        ull acc[NN] = {};
        #pragma unroll
        for (int kq = 0; kq < 3; kq++) {
            ulonglong2 w = ldg4(&g_enc4[(kq * 64 + c) * 4]);
            #pragma unroll
            for (int r = 0; r < NN; r++) {
                ulonglong2 a = lds4(&s->xt[r0 + r][4 * kq]);
                ffma2(acc[r], a.x, w.x);
                ffma2(acc[r], a.y, w.y);
            }
        }
        #pragma unroll
        for (int r = 0; r < NN; r++)
            s->A[r0 + r][c] = fmaxf(hsum(acc[r]) + bEnc, 0.f);
    }
    __syncthreads();
    gcn_fused(s->A, g_g1w4, s->Bv, bG1, r0, c, adje);
    __syncthreads();
    gcn_fused(s->Bv, g_g2w4, s->A, bG2, r0, c, adje);
    __syncthreads();

    // LSTM gate GEMM on tensor pipe: g[32][256] = A @ wihT + hx @ whhT  (tf32 mma)
    {
        const int w = tid >> 5, lane = tid & 31;
        const int row = lane >> 2, kc = lane & 3;
        float d[2][4][4];
        #pragma unroll
        for (int m = 0; m < 2; m++)
            #pragma unroll
            for (int nt = 0; nt < 4; nt++)
                #pragma unroll
                for (int q = 0; q < 4; q++) d[m][nt][q] = 0.f;

        #pragma unroll
        for (int kt = 0; kt < 8; kt++) {
            int k0 = kt * 8 + kc;
            uint32_t af[2][4], hf[2][4];
            #pragma unroll
            for (int m = 0; m < 2; m++) {
                int rb = m * 16 + row;
                af[m][0] = cvtt(s->A[rb][k0]);
                af[m][1] = cvtt(s->A[rb + 8][k0]);
                af[m][2] = cvtt(s->A[rb][k0 + 4]);
                af[m][3] = cvtt(s->A[rb + 8][k0 + 4]);
                hf[m][0] = cvtt(s->hx[rb][k0]);
                hf[m][1] = cvtt(s->hx[rb + 8][k0]);
                hf[m][2] = cvtt(s->hx[rb][k0 + 4]);
                hf[m][3] = cvtt(s->hx[rb + 8][k0 + 4]);
            }
            #pragma unroll
            for (int nt = 0; nt < 4; nt++) {
                int bi = ((kt * 32 + (w * 4 + nt)) * 32 + lane) * 2;
                ull bw = ldg2(&g_wihP[bi]);
                ull bh = ldg2(&g_whhP[bi]);
                uint32_t bw0 = (uint32_t)bw, bw1 = (uint32_t)(bw >> 32);
                uint32_t bh0 = (uint32_t)bh, bh1 = (uint32_t)(bh >> 32);
                mma8(d[0][nt], af[0], bw0, bw1);
                mma8(d[0][nt], hf[0], bh0, bh1);
                mma8(d[1][nt], af[1], bw0, bw1);
                mma8(d[1][nt], hf[1], bh0, bh1);
            }
        }
        // store D frags to g
        #pragma unroll
        for (int m = 0; m < 2; m++)
            #pragma unroll
            for (int nt = 0; nt < 4; nt++) {
                int rr = m * 16 + row, cc2 = (w * 4 + nt) * 8 + 2 * kc;
                *reinterpret_cast<float2*>(&s->g[rr][cc2]) =
                    make_float2(d[m][nt][0], d[m][nt][1]);
                *reinterpret_cast<float2*>(&s->g[rr + 8][cc2]) =
                    make_float2(d[m][nt][2], d[m][nt][3]);
            }
    }
    __syncthreads();

    // gate nonlinearity; cx in registers, hx -> smem
    #pragma unroll
    for (int r = 0; r < NN; r++) {
        int rr = r0 + r;
        float gi = sigm_f(s->g[rr][c]       + bI);
        float gf = sigm_f(s->g[rr][64 + c]  + bF);
        float gg = tanh_f(s->g[rr][128 + c] + bG);
        float go = sigm_f(s->g[rr][192 + c] + bO);
        float cc = gf * creg[r] + gi * gg;
        creg[r] = cc;
        s->hx[rr][c] = go * tanh_f(cc);
    }
    __syncthreads();
}

__global__ void __launch_bounds__(BT, 2)
stgnn_kernel(const float* __restrict__ xh,    const float* __restrict__ adj,
             const float* __restrict__ enc_b,
             const float* __restrict__ g1b,   const float* __restrict__ g2b,
             const float* __restrict__ b_ih,  const float* __restrict__ b_hh,
             const float* __restrict__ d1b,   const float* __restrict__ d2b,
             float* __restrict__ out) {
    extern __shared__ char smem_raw[];
    Smem* s = reinterpret_cast<Smem*>(smem_raw);
    const int tid = threadIdx.x;
    const int bb0 = blockIdx.x * EPB;
    const int e = tid >> 6, c = tid & 63;

    // hoisted per-thread biases
    const float bEnc = __ldg(&enc_b[c]);
    const float bG1  = __ldg(&g1b[c]);
    const float bG2  = __ldg(&g2b[c]);
    const float bI = __ldg(&b_ih[c])        + __ldg(&b_hh[c]);
    const float bF = __ldg(&b_ih[64 + c])   + __ldg(&b_hh[64 + c]);
    const float bG = __ldg(&b_ih[128 + c])  + __ldg(&b_hh[128 + c]);
    const float bO = __ldg(&b_ih[192 + c])  + __ldg(&b_hh[192 + c]);
    const float bD1 = __ldg(&d1b[tid & 31]);
    const float bD2 = (tid < RWS * DYNV) ? __ldg(&d2b[tid % DYNV]) : 0.f;

    // ---- zero A and hx (incl. pad rows 28..31) ----
    for (int idx = tid; idx < 32 * HS; idx += BT) {
        (&s->A[0][0])[idx]  = 0.f;
        (&s->hx[0][0])[idx] = 0.f;
    }
    // ---- normalized adjacency ----
    for (int idx = tid; idx < EPB * 49; idx += BT) {
        int ee = idx / 49, ij = idx - ee * 49;
        int i = ij / 7, j = ij - i * 7;
        s->adjn[ee][ij] = (i == j) ? 1.0f : __ldg(&adj[(bb0 + ee) * 49 + ij]);
    }
    float creg[NN];
    #pragma unroll
    for (int r = 0; r < NN; r++) creg[r] = 0.f;
    __syncthreads();
    if (tid < EPB * NN) {
        int ee = tid / NN, i = tid - ee * NN;
        float sum = 0.f;
        #pragma unroll
        for (int j = 0; j < NN; j++) sum += s->adjn[ee][i * 7 + j];
        s->deg[ee][i] = rsqrtf(fmaxf(sum, 1.0f));
    }
    __syncthreads();
    for (int idx = tid; idx < EPB * 49; idx += BT) {
        int ee = idx / 49, ij = idx - ee * 49;
        int i = ij / 7, j = ij - i * 7;
        s->adjn[ee][ij] *= s->deg[ee][i] * s->deg[ee][j];
    }
    __syncthreads();

    // ---- history scan ----
    #pragma unroll 1
    for (int t = 0; t < T_; t++) {
        for (int idx = tid; idx < RWS * 12; idx += BT) {
            int r = idx / 12, k = idx - r * 12;
            int ee = r / NN, n = r - ee * NN;
            float v = 0.f;
            if (k < INV) v = __ldg(&xh[(((bb0 + ee) * T_ + t) * NN + n) * INV + k]);
            s->xt[r][k] = v;
        }
        __syncthreads();
        cell(s, tid, creg, bEnc, bG1, bG2, bI, bF, bG, bO);
    }

    // ---- seed pred/stat from last history step ----
    for (int idx = tid; idx < RWS * INV; idx += BT) {
        int r = idx / INV, k = idx - r * INV;
        int ee = r / NN, n = r - ee * NN;
        float v = __ldg(&xh[(((bb0 + ee) * T_ + (T_ - 1)) * NN + n) * INV + k]);
        if (k < DYNV) s->pred[r][k] = v;
        else          s->stat[r][k - DYNV] = v;
    }
    __syncthreads();

    // ---- future rollout ----
    #pragma unroll 1
    for (int f = 0; f < FUT; f++) {
        for (int idx = tid; idx < RWS * 12; idx += BT) {
            int r = idx / 12, k = idx - r * 12;
            float v = 0.f;
            if (k < DYNV)     v = s->pred[r][k];
            else if (k < INV) v = s->stat[r][k - DYNV];
            s->xt[r][k] = v;
        }
        __syncthreads();
        cell(s, tid, creg, bEnc, bG1, bG2, bI, bF, bG, bO);

        // decoder layer 1: Bv[:, :32] = relu(hx @ d1w + d1b); 7 groups x 4 rows
        {
            int col = tid & 31, grp = tid >> 5;   // grp 0..7
            if (grp < 7) {
                int r0d = grp * 4;
                ull acc[4] = {};
                #pragma unroll
                for (int kq = 0; kq < 16; kq++) {
                    ulonglong2 w = ldg4(&g_d1w4[(kq * 32 + col) * 4]);
                    #pragma unroll
                    for (int i = 0; i < 4; i++) {
                        ulonglong2 a = lds4(&s->hx[r0d + i][4 * kq]);
                        ffma2(acc[i], a.x, w.x);
                        ffma2(acc[i], a.y, w.y);
                    }
                }
                #pragma unroll
                for (int i = 0; i < 4; i++)
                    s->Bv[r0d + i][col] = fmaxf(hsum(acc[i]) + bD1, 0.f);
            }
        }
        __syncthreads();

        // decoder layer 2 + residual + clip + output (168 threads)
        if (tid < RWS * DYNV) {
            int r = tid / DYNV, d = tid - r * DYNV;
            ull acc = 0;
            float z = 0.f;
            asm("mov.b64 %0, {%1, %1};" : "=l"(acc) : "f"(z));
            #pragma unroll
            for (int kp = 0; kp < 16; kp++)
                ffma2(acc, ldsm2(&s->Bv[r][2 * kp]), ldg2(&g_d2w2[(kp * 6 + d) * 2]));
            float res = tanh_f(hsum(acc) + bD2) * 0.05f;
            float p = fminf(fmaxf(s->pred[r][d] + res, 0.f), 1.f);
            s->pred[r][d] = p;
            int ee = r / NN, n = r - ee * NN;
            out[(((bb0 + ee) * FUT + f) * NN + n) * DYNV + d] = p;
        }
        __syncthreads();
    }
}

extern "C" void kernel_launch(void* const* d_in, const int* in_sizes, int n_in,
                              void* d_out, int out_size) {
    const float* xh    = (const float*)d_in[0];
    const float* adj   = (const float*)d_in[1];
    const float* enc_w = (const float*)d_in[2];
    const float* enc_b = (const float*)d_in[3];
    const float* g1w   = (const float*)d_in[4];
    const float* g1b   = (const float*)d_in[5];
    const float* g2w   = (const float*)d_in[6];
    const float* g2b   = (const float*)d_in[7];
    const float* w_ih  = (const float*)d_in[8];
    const float* w_hh  = (const float*)d_in[9];
    const float* b_ih  = (const float*)d_in[10];
    const float* b_hh  = (const float*)d_in[11];
    const float* d1w   = (const float*)d_in[12];
    const float* d1b   = (const float*)d_in[13];
    const float* d2w   = (const float*)d_in[14];
    const float* d2b   = (const float*)d_in[15];
    float* out = (float*)d_out;

    cudaFuncSetAttribute(stgnn_kernel, cudaFuncAttributeMaxDynamicSharedMemorySize,
                         (int)sizeof(Smem));
    pack_weights<<<(23488 + 255) / 256, 256>>>(w_ih, w_hh, g1w, g2w, enc_w, d1w, d2w);
    stgnn_kernel<<<B_ / EPB, BT, sizeof(Smem)>>>(
        xh, adj, enc_b, g1b, g2b, b_ih, b_hh, d1b, d2b, out);
}

// round 16
// speedup vs baseline: 2.5188x; 1.0821x over previous
#include <cuda_runtime.h>
#include <cuda_bf16.h>
#include <math.h>
#include <stdint.h>

#define B_    4096
#define T_    24
#define NN    7
#define DYNV  6
#define INV   11
#define FUT   48

#define EPB   4              // batch elements per block
#define RWS   28             // real rows = EPB * NN
#define BT    256            // threads per block (8 warps)
#define HS    68             // fp32 padded row stride
#define GS    260            // gate buffer row stride
#define AHS   72             // bf16 row stride (144B, 8B-aligned rows)

typedef unsigned long long ull;

// bf16 B-fragment-packed LSTM weights for m16n8k16:
// entry = (kt*32 + nt)*32 + lane; ull: lo = b-reg0 (k=2kc,2kc+1), hi = b-reg1 (k+8)
__device__ ull g_wihB[4 * 32 * 32];
__device__ ull g_whhB[4 * 32 * 32];
// fp32 quad-packed weights for FFMA2 paths
__device__ float g_g1w4[16 * 64 * 4];
__device__ float g_g2w4[16 * 64 * 4];
__device__ float g_enc4[3 * 64 * 4];
__device__ float g_d1w4[16 * 32 * 4];
__device__ float g_d2w2[16 * 6 * 2];

__device__ __forceinline__ uint32_t pk2(float lo, float hi) {
    __nv_bfloat162 h = __floats2bfloat162_rn(lo, hi);
    return *reinterpret_cast<uint32_t*>(&h);
}

__global__ void pack_weights(const float* __restrict__ w_ih, const float* __restrict__ w_hh,
                             const float* __restrict__ g1w,  const float* __restrict__ g2w,
                             const float* __restrict__ enc_w,
                             const float* __restrict__ d1w,  const float* __restrict__ d2w) {
    int i = blockIdx.x * blockDim.x + threadIdx.x;
    if (i < 4096) {
        int lane = i & 31, nt = (i >> 5) & 31, kt = i >> 10;
        int k0 = kt * 16 + 2 * (lane & 3);
        int n  = nt * 8 + (lane >> 2);
        uint32_t li = pk2(w_ih[n * 64 + k0],     w_ih[n * 64 + k0 + 1]);
        uint32_t hi = pk2(w_ih[n * 64 + k0 + 8], w_ih[n * 64 + k0 + 9]);
        g_wihB[i] = (ull)li | ((ull)hi << 32);
        uint32_t lh = pk2(w_hh[n * 64 + k0],     w_hh[n * 64 + k0 + 1]);
        uint32_t hh = pk2(w_hh[n * 64 + k0 + 8], w_hh[n * 64 + k0 + 9]);
        g_whhB[i] = (ull)lh | ((ull)hh << 32);
    } else if (i < 4096 + 4096) {
        int j = i - 4096;
        int q = j & 3, c = (j >> 2) & 63, kq = j >> 8;
        g_g1w4[j] = g1w[(4 * kq + q) * 64 + c];
        g_g2w4[j] = g2w[(4 * kq + q) * 64 + c];
    } else if (i < 8192 + 768) {
        int j = i - 8192;
        int q = j & 3, c = (j >> 2) & 63, kq = j >> 8;
        int k = 4 * kq + q;
        g_enc4[j] = (k < INV) ? enc_w[k * 64 + c] : 0.f;
    } else if (i < 8960 + 2048) {
        int j = i - 8960;
        int q = j & 3, c = (j >> 2) & 31, kq = j >> 7;
        g_d1w4[j] = d1w[(4 * kq + q) * 32 + c];
    } else if (i < 11008 + 192) {
        int j = i - 11008;
        int kp = j / 12, rr = j - kp * 12, d = rr >> 1, p = rr & 1;
        g_d2w2[j] = d2w[(2 * kp + p) * 6 + d];
    }
}

// ---------- helpers ----------
__device__ __forceinline__ ulonglong2 ldg4(const float* p) {
    return __ldg(reinterpret_cast<const ulonglong2*>(p));
}
__device__ __forceinline__ ulonglong2 lds4(const float* p) {
    return *reinterpret_cast<const ulonglong2*>(p);
}
__device__ __forceinline__ ull ldsm2(const float* p) { return *reinterpret_cast<const ull*>(p); }
__device__ __forceinline__ ull ldg2(const float* p)  { return __ldg(reinterpret_cast<const ull*>(p)); }
__device__ __forceinline__ void ffma2(ull& d, ull a, ull b) {
    asm("fma.rn.f32x2 %0, %1, %2, %3;" : "=l"(d) : "l"(a), "l"(b), "l"(d));
}
__device__ __forceinline__ float hsum(ull v) {
    float2 f = *reinterpret_cast<float2*>(&v);
    return f.x + f.y;
}
__device__ __forceinline__ void mma16b(float* d, const uint32_t* a, uint32_t b0, uint32_t b1) {
    asm("mma.sync.aligned.m16n8k16.row.col.f32.bf16.bf16.f32 "
        "{%0,%1,%2,%3},{%4,%5,%6,%7},{%8,%9},{%0,%1,%2,%3};"
        : "+f"(d[0]), "+f"(d[1]), "+f"(d[2]), "+f"(d[3])
        : "r"(a[0]), "r"(a[1]), "r"(a[2]), "r"(a[3]), "r"(b0), "r"(b1));
}
__device__ __forceinline__ float sigm_f(float x) { return __fdividef(1.f, 1.f + __expf(-x)); }
__device__ __forceinline__ float tanh_f(float x) {
    float e = __expf(2.f * x);
    return 1.f - __fdividef(2.f, e + 1.f);
}

struct __align__(16) Smem {
    float xt[RWS][12];
    float A[RWS][HS];
    float Bv[RWS][HS];
    float hx[RWS][HS];               // fp32 hx (decoder path)
    __nv_bfloat16 Ah[32][AHS];       // bf16 mma operand (rows 28..31 zero pad)
    __nv_bfloat16 hxh[32][AHS];      // bf16 mma operand (rows 28..31 zero pad)
    float g[32][GS];                 // gate pre-activations
    float adjn[EPB][49];
    float deg[EPB][8];
    float pred[RWS][DYNV];
    float stat[RWS][8];
};

// GCN layer fused (fp32 out): out[r0+i][c] = relu( sum_j adje[ij] * (in @ W)[r0+j][c] + bb )
__device__ __forceinline__ void gcn_fused(const float (*in)[HS], const float* __restrict__ w4,
                                          float (*out)[HS], float bb, int r0, int c,
                                          const float* adje) {
    ull acc[NN] = {};
    #pragma unroll
    for (int kq = 0; kq < 16; kq++) {
        ulonglong2 w = ldg4(&w4[(kq * 64 + c) * 4]);
        #pragma unroll
        for (int r = 0; r < NN; r++) {
            ulonglong2 a = lds4(&in[r0 + r][4 * kq]);
            ffma2(acc[r], a.x, w.x);
            ffma2(acc[r], a.y, w.y);
        }
    }
    float bv[NN];
    #pragma unroll
    for (int r = 0; r < NN; r++) bv[r] = hsum(acc[r]);
    #pragma unroll
    for (int i = 0; i < NN; i++) {
        float a = bb;
        #pragma unroll
        for (int j = 0; j < NN; j++)
            a = fmaf(adje[i * 7 + j], bv[j], a);
        out[r0 + i][c] = fmaxf(a, 0.f);
    }
}

// GCN layer fused, bf16 output at permuted column posc (mma operand layout)
__device__ __forceinline__ void gcn_fused_h(const float (*in)[HS], const float* __restrict__ w4,
                                            __nv_bfloat16 (*outh)[AHS], float bb, int r0,
                                            int c, int posc, const float* adje) {
    ull acc[NN] = {};
    #pragma unroll
    for (int kq = 0; kq < 16; kq++) {
        ulonglong2 w = ldg4(&w4[(kq * 64 + c) * 4]);
        #pragma unroll
        for (int r = 0; r < NN; r++) {
            ulonglong2 a = lds4(&in[r0 + r][4 * kq]);
            ffma2(acc[r], a.x, w.x);
            ffma2(acc[r], a.y, w.y);
        }
    }
    float bv[NN];
    #pragma unroll
    for (int r = 0; r < NN; r++) bv[r] = hsum(acc[r]);
    #pragma unroll
    for (int i = 0; i < NN; i++) {
        float a = bb;
        #pragma unroll
        for (int j = 0; j < NN; j++)
            a = fmaf(adje[i * 7 + j], bv[j], a);
        outh[r0 + i][posc] = __float2bfloat16_rn(fmaxf(a, 0.f));
    }
}

// One cell step. xt filled+synced on entry; hx/hxh/creg updated+synced on exit.
__device__ __forceinline__ void cell(Smem* s, int tid, int posc, float* creg,
        float bEnc, float bG1, float bG2,
        float bI, float bF, float bG, float bO) {
    const int e = tid >> 6, c = tid & 63, r0 = e * NN;
    const float* adje = &s->adjn[e][0];

    // encoder -> A (fp32)
    {
        ull acc[NN] = {};
        #pragma unroll
        for (int kq = 0; kq < 3; kq++) {
            ulonglong2 w = ldg4(&g_enc4[(kq * 64 + c) * 4]);
            #pragma unroll
            for (int r = 0; r < NN; r++) {
                ulonglong2 a = lds4(&s->xt[r0 + r][4 * kq]);
                ffma2(acc[r], a.x, w.x);
                ffma2(acc[r], a.y, w.y);
            }
        }
        #pragma unroll
        for (int r = 0; r < NN; r++)
            s->A[r0 + r][c] = fmaxf(hsum(acc[r]) + bEnc, 0.f);
    }
    __syncthreads();
    gcn_fused(s->A, g_g1w4, s->Bv, bG1, r0, c, adje);            // A -> Bv (fp32)
    __syncthreads();
    gcn_fused_h(s->Bv, g_g2w4, s->Ah, bG2, r0, c, posc, adje);   // Bv -> Ah (bf16, permuted)
    __syncthreads();

    // LSTM gate GEMM on tensor pipe: g[32][256] = Ah @ wihT + hxh @ whhT (bf16 m16n8k16)
    {
        const int w = tid >> 5, lane = tid & 31;
        const int row = lane >> 2, kc = lane & 3;
        float d[2][4][4];
        #pragma unroll
        for (int m = 0; m < 2; m++)
            #pragma unroll
            for (int nt = 0; nt < 4; nt++)
                #pragma unroll
                for (int q = 0; q < 4; q++) d[m][nt][q] = 0.f;

        #pragma unroll
        for (int kt = 0; kt < 4; kt++) {
            int off = kt * 16 + 4 * kc;     // permuted: holds logical {2kc,2kc+1,8+2kc,9+2kc}
            uint32_t af[2][4], hf[2][4];
            #pragma unroll
            for (int m = 0; m < 2; m++) {
                int rb = m * 16 + row;
                ull va0 = *reinterpret_cast<const ull*>(&s->Ah[rb][off]);
                ull va1 = *reinterpret_cast<const ull*>(&s->Ah[rb + 8][off]);
                ull vh0 = *reinterpret_cast<const ull*>(&s->hxh[rb][off]);
                ull vh1 = *reinterpret_cast<const ull*>(&s->hxh[rb + 8][off]);
                af[m][0] = (uint32_t)va0; af[m][1] = (uint32_t)va1;
                af[m][2] = (uint32_t)(va0 >> 32); af[m][3] = (uint32_t)(va1 >> 32);
                hf[m][0] = (uint32_t)vh0; hf[m][1] = (uint32_t)vh1;
                hf[m][2] = (uint32_t)(vh0 >> 32); hf[m][3] = (uint32_t)(vh1 >> 32);
            }
            #pragma unroll
            for (int nt = 0; nt < 4; nt++) {
                int bi = (kt * 32 + (w * 4 + nt)) * 32 + lane;
                ull bw = __ldg(&g_wihB[bi]);
                ull bh = __ldg(&g_whhB[bi]);
                uint32_t bw0 = (uint32_t)bw, bw1 = (uint32_t)(bw >> 32);
                uint32_t bh0 = (uint32_t)bh, bh1 = (uint32_t)(bh >> 32);
                mma16b(d[0][nt], af[0], bw0, bw1);
                mma16b(d[0][nt], hf[0], bh0, bh1);
                mma16b(d[1][nt], af[1], bw0, bw1);
                mma16b(d[1][nt], hf[1], bh0, bh1);
            }
        }
        // store D frags to g
        #pragma unroll
        for (int m = 0; m < 2; m++)
            #pragma unroll
            for (int nt = 0; nt < 4; nt++) {
                int rr = m * 16 + row, cc2 = (w * 4 + nt) * 8 + 2 * kc;
                *reinterpret_cast<float2*>(&s->g[rr][cc2]) =
                    make_float2(d[m][nt][0], d[m][nt][1]);
                *reinterpret_cast<float2*>(&s->g[rr + 8][cc2]) =
                    make_float2(d[m][nt][2], d[m][nt][3]);
            }
    }
    __syncthreads();

    // gate nonlinearity; cx in registers, hx -> fp32 smem + bf16 mma copy
    #pragma unroll
    for (int r = 0; r < NN; r++) {
        int rr = r0 + r;
        float gi = sigm_f(s->g[rr][c]       + bI);
        float gf = sigm_f(s->g[rr][64 + c]  + bF);
        float gg = tanh_f(s->g[rr][128 + c] + bG);
        float go = sigm_f(s->g[rr][192 + c] + bO);
        float cc = gf * creg[r] + gi * gg;
        creg[r] = cc;
        float h = go * tanh_f(cc);
        s->hx[rr][c] = h;
        s->hxh[rr][posc] = __float2bfloat16_rn(h);
    }
    __syncthreads();
}

__global__ void __launch_bounds__(BT, 2)
stgnn_kernel(const float* __restrict__ xh,    const float* __restrict__ adj,
             const float* __restrict__ enc_b,
             const float* __restrict__ g1b,   const float* __restrict__ g2b,
             const float* __restrict__ b_ih,  const float* __restrict__ b_hh,
             const float* __restrict__ d1b,   const float* __restrict__ d2b,
             float* __restrict__ out) {
    extern __shared__ char smem_raw[];
    Smem* s = reinterpret_cast<Smem*>(smem_raw);
    const int tid = threadIdx.x;
    const int bb0 = blockIdx.x * EPB;
    const int c = tid & 63;

    // permuted column for bf16 operand writes: within k16 tile,
    // logical j -> phys 4*((j&7)>>1) + 2*(j>>3) + (j&1)
    const int jj = c & 15;
    const int posc = (c & 48) + 4 * ((jj & 7) >> 1) + 2 * (jj >> 3) + (jj & 1);

    // hoisted per-thread biases
    const float bEnc = __ldg(&enc_b[c]);
    const float bG1  = __ldg(&g1b[c]);
    const float bG2  = __ldg(&g2b[c]);
    const float bI = __ldg(&b_ih[c])        + __ldg(&b_hh[c]);
    const float bF = __ldg(&b_ih[64 + c])   + __ldg(&b_hh[64 + c]);
    const float bG = __ldg(&b_ih[128 + c])  + __ldg(&b_hh[128 + c]);
    const float bO = __ldg(&b_ih[192 + c])  + __ldg(&b_hh[192 + c]);
    const float bD1 = __ldg(&d1b[tid & 31]);
    const float bD2 = (tid < RWS * DYNV) ? __ldg(&d2b[tid % DYNV]) : 0.f;

    // ---- zero bf16 operand buffers (incl. pad rows) + fp32 hx ----
    for (int idx = tid; idx < 32 * AHS; idx += BT) {
        (&s->Ah[0][0])[idx]  = __float2bfloat16_rn(0.f);
        (&s->hxh[0][0])[idx] = __float2bfloat16_rn(0.f);
    }
    for (int idx = tid; idx < RWS * HS; idx += BT)
        (&s->hx[0][0])[idx] = 0.f;
    // ---- normalized adjacency ----
    for (int idx = tid; idx < EPB * 49; idx += BT) {
        int ee = idx / 49, ij = idx - ee * 49;
        int i = ij / 7, j = ij - i * 7;
        s->adjn[ee][ij] = (i == j) ? 1.0f : __ldg(&adj[(bb0 + ee) * 49 + ij]);
    }
    float creg[NN];
    #pragma unroll
    for (int r = 0; r < NN; r++) creg[r] = 0.f;
    __syncthreads();
    if (tid < EPB * NN) {
        int ee = tid / NN, i = tid - ee * NN;
        float sum = 0.f;
        #pragma unroll
        for (int j = 0; j < NN; j++) sum += s->adjn[ee][i * 7 + j];
        s->deg[ee][i] = rsqrtf(fmaxf(sum, 1.0f));
    }
    __syncthreads();
    for (int idx = tid; idx < EPB * 49; idx += BT) {
        int ee = idx / 49, ij = idx - ee * 49;
        int i = ij / 7, j = ij - i * 7;
        s->adjn[ee][ij] *= s->deg[ee][i] * s->deg[ee][j];
    }
    __syncthreads();

    // ---- history scan ----
    #pragma unroll 1
    for (int t = 0; t < T_; t++) {
        for (int idx = tid; idx < RWS * 12; idx += BT) {
            int r = idx / 12, k = idx - r * 12;
            int ee = r / NN, n = r - ee * NN;
            float v = 0.f;
            if (k < INV) v = __ldg(&xh[(((bb0 + ee) * T_ + t) * NN + n) * INV + k]);
            s->xt[r][k] = v;
        }
        __syncthreads();
        cell(s, tid, posc, creg, bEnc, bG1, bG2, bI, bF, bG, bO);
    }

    // ---- seed pred/stat from last history step ----
    for (int idx = tid; idx < RWS * INV; idx += BT) {
        int r = idx / INV, k = idx - r * INV;
        int ee = r / NN, n = r - ee * NN;
        float v = __ldg(&xh[(((bb0 + ee) * T_ + (T_ - 1)) * NN + n) * INV + k]);
        if (k < DYNV) s->pred[r][k] = v;
        else          s->stat[r][k - DYNV] = v;
    }
    __syncthreads();

    // ---- future rollout ----
    #pragma unroll 1
    for (int f = 0; f < FUT; f++) {
        for (int idx = tid; idx < RWS * 12; idx += BT) {
            int r = idx / 12, k = idx - r * 12;
            float v = 0.f;
            if (k < DYNV)     v = s->pred[r][k];
            else if (k < INV) v = s->stat[r][k - DYNV];
            s->xt[r][k] = v;
        }
        __syncthreads();
        cell(s, tid, posc, creg, bEnc, bG1, bG2, bI, bF, bG, bO);

        // decoder layer 1: Bv[:, :32] = relu(hx @ d1w + d1b); 7 groups x 4 rows
        {
            int col = tid & 31, grp = tid >> 5;   // grp 0..7
            if (grp < 7) {
                int r0d = grp * 4;
                ull acc[4] = {};
                #pragma unroll
                for (int kq = 0; kq < 16; kq++) {
                    ulonglong2 w = ldg4(&g_d1w4[(kq * 32 + col) * 4]);
                    #pragma unroll
                    for (int i = 0; i < 4; i++) {
                        ulonglong2 a = lds4(&s->hx[r0d + i][4 * kq]);
                        ffma2(acc[i], a.x, w.x);
                        ffma2(acc[i], a.y, w.y);
                    }
                }
                #pragma unroll
                for (int i = 0; i < 4; i++)
                    s->Bv[r0d + i][col] = fmaxf(hsum(acc[i]) + bD1, 0.f);
            }
        }
        __syncthreads();

        // decoder layer 2 + residual + clip + output (168 threads)
        if (tid < RWS * DYNV) {
            int r = tid / DYNV, d = tid - r * DYNV;
            ull acc = 0;
            float z = 0.f;
            asm("mov.b64 %0, {%1, %1};" : "=l"(acc) : "f"(z));
            #pragma unroll
            for (int kp = 0; kp < 16; kp++)
                ffma2(acc, ldsm2(&s->Bv[r][2 * kp]), ldg2(&g_d2w2[(kp * 6 + d) * 2]));
            float res = tanh_f(hsum(acc) + bD2) * 0.05f;
            float p = fminf(fmaxf(s->pred[r][d] + res, 0.f), 1.f);
            s->pred[r][d] = p;
            int ee = r / NN, n = r - ee * NN;
            out[(((bb0 + ee) * FUT + f) * NN + n) * DYNV + d] = p;
        }
        __syncthreads();
    }
}

extern "C" void kernel_launch(void* const* d_in, const int* in_sizes, int n_in,
                              void* d_out, int out_size) {
    const float* xh    = (const float*)d_in[0];
    const float* adj   = (const float*)d_in[1];
    const float* enc_w = (const float*)d_in[2];
    const float* enc_b = (const float*)d_in[3];
    const float* g1w   = (const float*)d_in[4];
    const float* g1b   = (const float*)d_in[5];
    const float* g2w   = (const float*)d_in[6];
    const float* g2b   = (const float*)d_in[7];
    const float* w_ih  = (const float*)d_in[8];
    const float* w_hh  = (const float*)d_in[9];
    const float* b_ih  = (const float*)d_in[10];
    const float* b_hh  = (const float*)d_in[11];
    const float* d1w   = (const float*)d_in[12];
    const float* d1b   = (const float*)d_in[13];
    const float* d2w   = (const float*)d_in[14];
    const float* d2b   = (const float*)d_in[15];
    float* out = (float*)d_out;

    cudaFuncSetAttribute(stgnn_kernel, cudaFuncAttributeMaxDynamicSharedMemorySize,
                         (int)sizeof(Smem));
    pack_weights<<<(11200 + 255) / 256, 256>>>(w_ih, w_hh, g1w, g2w, enc_w, d1w, d2w);
    stgnn_kernel<<<B_ / EPB, BT, sizeof(Smem)>>>(
        xh, adj, enc_b, g1b, g2b, b_ih, b_hh, d1b, d2b, out);
}